// round 14
// baseline (speedup 1.0000x reference)
#include <cuda_runtime.h>
#include <cuda_bf16.h>
#include <cstdint>

#define BB 4
#define TT 4096
#define DIN 1024
#define HH 64
#define MROWS (BB*TT)

// bf16 hi/lo split scratch
__device__ __nv_bfloat16 g_qh[(size_t)MROWS*HH], g_ql[(size_t)MROWS*HH];
__device__ __nv_bfloat16 g_kh[(size_t)MROWS*HH], g_kl[(size_t)MROWS*HH];
__device__ __nv_bfloat16 g_vth[(size_t)MROWS*HH], g_vtl[(size_t)MROWS*HH]; // [b][h][t]
// pre-converted inputs
__device__ __nv_bfloat16 g_xh[(size_t)MROWS*DIN], g_xl[(size_t)MROWS*DIN];
__device__ __nv_bfloat16 g_wh[3*HH*DIN], g_wl[3*HH*DIN];
// attention accumulators (fp32)
__device__ float g_O[(size_t)MROWS*HH];
__device__ float g_ell[MROWS];
// dynamic work ticket
__device__ unsigned int g_ticket;

#define NCHUNK 576

// ---------------- helpers ----------------
__device__ __forceinline__ void mma_bf16(float* d, const uint32_t* a,
                                         uint32_t b0, uint32_t b1) {
    asm volatile(
        "mma.sync.aligned.m16n8k16.row.col.f32.bf16.bf16.f32 "
        "{%0,%1,%2,%3}, {%4,%5,%6,%7}, {%8,%9}, {%0,%1,%2,%3};"
        : "+f"(d[0]), "+f"(d[1]), "+f"(d[2]), "+f"(d[3])
        : "r"(a[0]), "r"(a[1]), "r"(a[2]), "r"(a[3]), "r"(b0), "r"(b1));
}

__device__ __forceinline__ void ldsm_x4(uint32_t& r0, uint32_t& r1,
                                        uint32_t& r2, uint32_t& r3, uint32_t a) {
    asm volatile("ldmatrix.sync.aligned.m8n8.x4.shared.b16 {%0,%1,%2,%3}, [%4];"
                 : "=r"(r0), "=r"(r1), "=r"(r2), "=r"(r3) : "r"(a));
}

__device__ __forceinline__ void split_pair(float x, float y,
                                           uint32_t& h, uint32_t& l) {
    __nv_bfloat162 hv = __floats2bfloat162_rn(x, y);
    float hx = __bfloat162float(hv.x);
    float hy = __bfloat162float(hv.y);
    __nv_bfloat162 lv = __floats2bfloat162_rn(x - hx, y - hy);
    h = *reinterpret_cast<uint32_t*>(&hv);
    l = *reinterpret_cast<uint32_t*>(&lv);
}

__device__ __forceinline__ uint32_t smem_u32(const void* p) {
    uint32_t a;
    asm("{ .reg .u64 t; cvta.to.shared.u64 t, %1; cvt.u32.u64 %0, t; }"
        : "=r"(a) : "l"(p));
    return a;
}

__device__ __forceinline__ void cpa16(uint32_t dst, const void* src) {
    asm volatile("cp.async.cg.shared.global [%0], [%1], 16;"
                 :: "r"(dst), "l"(src) : "memory");
}
#define CPA_COMMIT() asm volatile("cp.async.commit_group;" ::: "memory")
#define CPA_WAIT(N)  asm volatile("cp.async.wait_group %0;" :: "n"(N) : "memory")

__device__ __forceinline__ void redg_v2(float* p, float a, float b) {
    asm volatile("red.global.add.v2.f32 [%0], {%1, %2};"
                 :: "l"(p), "f"(a), "f"(b) : "memory");
}

#define RS 144   // smem row stride bytes

// ============================================================================
// Dummy kernel (ncu launch-index alignment)
// ============================================================================
__global__ void dummy_kernel() {}

// ============================================================================
// Pre-convert + zero accumulators + reset ticket
// ============================================================================
__global__ __launch_bounds__(256) void convert_kernel(
    const float* __restrict__ x,
    const float* __restrict__ Wq, const float* __restrict__ Wk,
    const float* __restrict__ Wv)
{
    const size_t tid0 = (size_t)blockIdx.x * 256 + threadIdx.x;
    const size_t stride = (size_t)gridDim.x * 256;
    if (tid0 == 0) g_ticket = 0;
    const size_t NX = (size_t)MROWS * DIN / 4;
    for (size_t t = tid0; t < NX; t += stride) {
        float4 v = ((const float4*)x)[t];
        uint32_t h0, l0, h1, l1;
        split_pair(v.x, v.y, h0, l0);
        split_pair(v.z, v.w, h1, l1);
        ((uint2*)g_xh)[t] = make_uint2(h0, h1);
        ((uint2*)g_xl)[t] = make_uint2(l0, l1);
    }
    const size_t NW = (size_t)HH * DIN / 4;
    for (size_t t = tid0; t < 3 * NW; t += stride) {
        const int set = (int)(t / NW);
        const size_t o = t - (size_t)set * NW;
        const float* W = (set == 0) ? Wq : (set == 1) ? Wk : Wv;
        float4 v = ((const float4*)W)[o];
        uint32_t h0, l0, h1, l1;
        split_pair(v.x, v.y, h0, l0);
        split_pair(v.z, v.w, h1, l1);
        ((uint2*)g_wh)[t] = make_uint2(h0, h1);
        ((uint2*)g_wl)[t] = make_uint2(l0, l1);
    }
    const float4 z4 = make_float4(0.f, 0.f, 0.f, 0.f);
    const size_t NO = (size_t)MROWS * HH / 4;
    for (size_t t = tid0; t < NO; t += stride) ((float4*)g_O)[t] = z4;
    for (size_t t = tid0; t < MROWS / 4; t += stride) ((float4*)g_ell)[t] = z4;
}

// ============================================================================
// Projection: grid=(128,3), 256 thr, 2 CTAs/SM, cp.async double buffer + ldsm.
// (unchanged — measured at its HMMA floor)
// ============================================================================
#define P_XH 0
#define P_XL (128*RS)
#define P_WH (256*RS)
#define P_WL (256*RS + 64*RS)
#define PBUF (384*RS)
#define PROJ_SMEM (2*PBUF)

__global__ __launch_bounds__(256, 2) void proj_kernel(
    const float* __restrict__ bq, const float* __restrict__ bk,
    const float* __restrict__ bv)
{
    extern __shared__ char smp[];
    __shared__ float s_bias[64];
    const uint32_t sbase = smem_u32(smp);

    const int tid = threadIdx.x;
    const int wid = tid >> 5, lane = tid & 31;
    const int g = lane >> 2, tg = lane & 3;
    const int m0 = blockIdx.x * 128;
    const int my = blockIdx.y;

    const float* bias = (my == 0) ? bq : (my == 1) ? bk : bv;
    if (tid < 64) s_bias[tid] = bias[tid];

    const size_t wset = (size_t)my * HH * DIN;

    auto stage = [&](int kc, int bi) {
        const int k0 = kc * 64;
        const uint32_t bb = sbase + bi * PBUF;
#pragma unroll
        for (int u = tid; u < 3072; u += 256) {
            uint32_t dst; const void* src;
            if (u < 2048) {
                const int comp = u >> 10;
                const int idx = u & 1023;
                const int r = idx >> 3, c8 = idx & 7;
                const __nv_bfloat16* gsrc = comp ? g_xl : g_xh;
                src = gsrc + (size_t)(m0 + r) * DIN + k0 + c8 * 8;
                dst = bb + (comp ? P_XL : P_XH) + r * RS + c8 * 16;
            } else {
                const int comp = (u - 2048) >> 9;
                const int idx = (u - 2048) & 511;
                const int r = idx >> 3, c8 = idx & 7;
                const __nv_bfloat16* gsrc = comp ? g_wl : g_wh;
                src = gsrc + wset + (size_t)r * DIN + k0 + c8 * 8;
                dst = bb + (comp ? P_WL : P_WH) + r * RS + c8 * 16;
            }
            cpa16(dst, src);
        }
        CPA_COMMIT();
    };

    const uint32_t aoff = (lane & 7) * RS + ((lane >> 3) & 1) * 8 * RS
                        + ((lane >> 4) & 1) * 16;
    const uint32_t boff = (lane & 7) * RS + ((lane >> 4) & 1) * 8 * RS
                        + ((lane >> 3) & 1) * 16;

    float acc[8][4];
#pragma unroll
    for (int n = 0; n < 8; ++n)
#pragma unroll
        for (int q = 0; q < 4; ++q) acc[n][q] = 0.f;

    stage(0, 0);
    for (int kc = 0; kc < 16; ++kc) {
        CPA_WAIT(0);
        __syncthreads();
        if (kc < 15) stage(kc + 1, (kc + 1) & 1);

        const uint32_t bb = sbase + (kc & 1) * PBUF;
        const uint32_t Xh = bb + P_XH, Xl = bb + P_XL;
        const uint32_t Wh = bb + P_WH, Wl = bb + P_WL;
        const int ra = wid * 16;

#pragma unroll
        for (int ks = 0; ks < 4; ++ks) {
            uint32_t ah[4], al[4];
            ldsm_x4(ah[0], ah[1], ah[2], ah[3], Xh + ra * RS + ks * 32 + aoff);
            ldsm_x4(al[0], al[1], al[2], al[3], Xl + ra * RS + ks * 32 + aoff);
#pragma unroll
            for (int p = 0; p < 4; ++p) {
                uint32_t h0, h1, h2, h3, l0, l1, l2, l3;
                ldsm_x4(h0, h1, h2, h3, Wh + p * 16 * RS + ks * 32 + boff);
                ldsm_x4(l0, l1, l2, l3, Wl + p * 16 * RS + ks * 32 + boff);
                mma_bf16(acc[2*p],   ah, h0, h1);
                mma_bf16(acc[2*p],   al, h0, h1);
                mma_bf16(acc[2*p],   ah, l0, l1);
                mma_bf16(acc[2*p+1], ah, h2, h3);
                mma_bf16(acc[2*p+1], al, h2, h3);
                mma_bf16(acc[2*p+1], ah, l2, l3);
            }
        }
        __syncthreads();
    }

    // epilogue
    const int rA = m0 + wid * 16 + g;
    const int rB = rA + 8;
#pragma unroll
    for (int n = 0; n < 8; ++n) {
        const int col = 8 * n + 2 * tg;
        float v0 = acc[n][0] + s_bias[col];
        float v1 = acc[n][1] + s_bias[col + 1];
        float v2 = acc[n][2] + s_bias[col];
        float v3 = acc[n][3] + s_bias[col + 1];
        if (my < 2) {
            uint32_t h01, l01, h23, l23;
            split_pair(v0, v1, h01, l01);
            split_pair(v2, v3, h23, l23);
            __nv_bfloat16* oh = (my == 0) ? g_qh : g_kh;
            __nv_bfloat16* ol = (my == 0) ? g_ql : g_kl;
            *(uint32_t*)(oh + (size_t)rA * 64 + col) = h01;
            *(uint32_t*)(ol + (size_t)rA * 64 + col) = l01;
            *(uint32_t*)(oh + (size_t)rB * 64 + col) = h23;
            *(uint32_t*)(ol + (size_t)rB * 64 + col) = l23;
        } else {
            const int bA = rA >> 12, tA = rA & 4095;
            const int bB = rB >> 12, tB = rB & 4095;
            __nv_bfloat16 h;
            h = __float2bfloat16_rn(v0);
            g_vth[(size_t)(bA*64 + col  )*4096 + tA] = h;
            g_vtl[(size_t)(bA*64 + col  )*4096 + tA] = __float2bfloat16_rn(v0 - __bfloat162float(h));
            h = __float2bfloat16_rn(v1);
            g_vth[(size_t)(bA*64 + col+1)*4096 + tA] = h;
            g_vtl[(size_t)(bA*64 + col+1)*4096 + tA] = __float2bfloat16_rn(v1 - __bfloat162float(h));
            h = __float2bfloat16_rn(v2);
            g_vth[(size_t)(bB*64 + col  )*4096 + tB] = h;
            g_vtl[(size_t)(bB*64 + col  )*4096 + tB] = __float2bfloat16_rn(v2 - __bfloat162float(h));
            h = __float2bfloat16_rn(v3);
            g_vth[(size_t)(bB*64 + col+1)*4096 + tB] = h;
            g_vtl[(size_t)(bB*64 + col+1)*4096 + tB] = __float2bfloat16_rn(v3 - __bfloat162float(h));
        }
    }
}

// ============================================================================
// Attention: persistent CTAs, i-block = 128 rows, 4 warps x TWO 16-row
// m-tiles each (rows lw*16 and 64+lw*16) -> Q/V fragments feed both tiles
// (B-LDSM per MMA halved). Split-phase Q/V prefetch, K resident, fused
// exp->PV, diag kt-skip. 128 thr, 2 CTAs/SM, dynamic tickets.
// ============================================================================
#define AK   (2*128*RS)                 // 36864: Kh,Kl (128 rows)
#define AQ   (2*64*RS)                  // Qh,Ql
#define AV   (2*64*RS)                  // Vh,Vl
#define ATTN_SMEM (AK + AQ + AV)        // 73728 -> 2 CTAs/SM

__global__ __launch_bounds__(128, 2) void attn_kernel()
{
    extern __shared__ char smp[];
    __shared__ unsigned int s_tk;
    const uint32_t sbase = smem_u32(smp);
    const int tid = threadIdx.x;
    const int lw  = tid >> 5;
    const int lane = tid & 31;
    const int g  = lane >> 2, tg = lane & 3;

    const uint32_t Kb = sbase;
    const uint32_t Qb = sbase + AK;
    const uint32_t Vb = sbase + AK + AQ;

    const uint32_t aoff = (lane & 7) * RS + ((lane >> 3) & 1) * 8 * RS
                        + ((lane >> 4) & 1) * 16;
    const uint32_t boff = (lane & 7) * RS + ((lane >> 4) & 1) * 8 * RS
                        + ((lane >> 3) & 1) * 16;

    for (;;) {
        if (tid == 0) s_tk = atomicAdd(&g_ticket, 1u);
        __syncthreads();
        const unsigned int tk = s_tk;
        __syncthreads();
        if (tk >= NCHUNK) return;

        const int b   = tk & 3;
        const int cid = 143 - (int)(tk >> 2);       // heavy chunks first
        int kk = 1;
        while (2 * kk * (kk + 1) <= cid) ++kk;
        const int off = cid - 2 * kk * (kk - 1);
        const int ib  = 4 * (kk - 1) + off / kk;    // i-block (128 rows)
        const int jc  = off % kk;
        const int jt0 = jc * 8;
        const int jt1 = min(jt0 + 8, 2 * ib + 2);
        const int i0  = ib * 128;
        const int row0 = i0 + lw * 16 + g;          // m-tile 0
        const int row1 = row0 + 64;                 // m-tile 1

        // ---- stage K (128 rows, hi+lo; shares commit group with Q(jt0)) ----
#pragma unroll
        for (int i = tid; i < 2048; i += 128) {
            const int comp = i >> 10;
            const int idx = i & 1023;
            const int r = idx >> 3, c8 = idx & 7;
            const __nv_bfloat16* gsrc = comp ? g_kl : g_kh;
            cpa16(Kb + comp * (128 * RS) + r * RS + c8 * 16,
                  gsrc + (size_t)(b * 4096 + i0 + r) * 64 + c8 * 8);
        }

        auto stageQ = [&](int jt) {
            const int j0 = jt * 64;
#pragma unroll
            for (int i = tid; i < 1024; i += 128) {
                const int comp = i >> 9;
                const int idx = i & 511;
                const int r = idx >> 3, c8 = idx & 7;
                const __nv_bfloat16* gsrc = comp ? g_ql : g_qh;
                cpa16(Qb + comp * (64 * RS) + r * RS + c8 * 16,
                      gsrc + (size_t)(b * 4096 + j0 + r) * 64 + c8 * 8);
            }
            CPA_COMMIT();
        };
        auto stageV = [&](int jt) {
            const int j0 = jt * 64;
#pragma unroll
            for (int i = tid; i < 1024; i += 128) {
                const int comp = i >> 9;
                const int idx = i & 511;
                const int r = idx >> 3, c8 = idx & 7;
                const __nv_bfloat16* gsrc = comp ? g_vtl : g_vth;
                cpa16(Vb + comp * (64 * RS) + r * RS + c8 * 16,
                      gsrc + (size_t)(b * 64 + r) * 4096 + j0 + c8 * 8);
            }
            CPA_COMMIT();
        };

        float o0[8][4], o1[8][4];
#pragma unroll
        for (int n = 0; n < 8; ++n)
#pragma unroll
            for (int q = 0; q < 4; ++q) { o0[n][q] = 0.f; o1[n][q] = 0.f; }
        float ellA0 = 0.f, ellB0 = 0.f, ellA1 = 0.f, ellB1 = 0.f;

        stageQ(jt0);     // group: K+Q(jt0)
        stageV(jt0);     // group: V(jt0)

        for (int jt = jt0; jt < jt1; ++jt) {
            const int j0 = jt * 64;
            const bool more = (jt + 1 < jt1);
            // m-tile activity: tile0 rows lw*16..+15 -> only j0 <= i0 tiles
            const bool act0 = (j0 <= i0 + lw * 16 + 15);
            const bool diag0 = (j0 == i0);
            const bool diag1 = (j0 == i0 + 64);

            CPA_WAIT(1);     // K(first)+Q(jt) done; V(jt) may be in flight
            __syncthreads();

            const uint32_t Qh = Qb, Ql = Qb + 64 * RS;
            const uint32_t Vh = Vb, Vl = Vb + 64 * RS;

            // ---- S = K . Q^T for both m-tiles (shared Q fragments) ----
            float s0[8][4], s1[8][4];
#pragma unroll
            for (int n = 0; n < 8; ++n)
#pragma unroll
                for (int q = 0; q < 4; ++q) { s0[n][q] = 0.f; s1[n][q] = 0.f; }

#pragma unroll
            for (int ks = 0; ks < 4; ++ks) {
                uint32_t kh0[4], kl0[4], kh1[4], kl1[4];
                if (act0) {
                    ldsm_x4(kh0[0], kh0[1], kh0[2], kh0[3],
                            Kb + (lw * 16) * RS + ks * 32 + aoff);
                    ldsm_x4(kl0[0], kl0[1], kl0[2], kl0[3],
                            Kb + 128 * RS + (lw * 16) * RS + ks * 32 + aoff);
                }
                ldsm_x4(kh1[0], kh1[1], kh1[2], kh1[3],
                        Kb + (64 + lw * 16) * RS + ks * 32 + aoff);
                ldsm_x4(kl1[0], kl1[1], kl1[2], kl1[3],
                        Kb + 128 * RS + (64 + lw * 16) * RS + ks * 32 + aoff);
#pragma unroll
                for (int p = 0; p < 4; ++p) {
                    uint32_t h0, h1, h2, h3, l0, l1, l2, l3;
                    ldsm_x4(h0, h1, h2, h3, Qh + p * 16 * RS + ks * 32 + boff);
                    ldsm_x4(l0, l1, l2, l3, Ql + p * 16 * RS + ks * 32 + boff);
                    if (act0) {
                        mma_bf16(s0[2*p],   kh0, h0, h1);
                        mma_bf16(s0[2*p],   kl0, h0, h1);
                        mma_bf16(s0[2*p],   kh0, l0, l1);
                        mma_bf16(s0[2*p+1], kh0, h2, h3);
                        mma_bf16(s0[2*p+1], kl0, h2, h3);
                        mma_bf16(s0[2*p+1], kh0, l2, l3);
                    }
                    mma_bf16(s1[2*p],   kh1, h0, h1);
                    mma_bf16(s1[2*p],   kl1, h0, h1);
                    mma_bf16(s1[2*p],   kh1, l0, l1);
                    mma_bf16(s1[2*p+1], kh1, h2, h3);
                    mma_bf16(s1[2*p+1], kl1, h2, h3);
                    mma_bf16(s1[2*p+1], kh1, l2, l3);
                }
            }

            // Q consumed -> prefetch Q(jt+1)
            __syncthreads();
            if (more) stageQ(jt + 1);

            // wait for V(jt); Q(jt+1) (if any) stays in flight
            if (more) { CPA_WAIT(1); } else { CPA_WAIT(0); }
            __syncthreads();

            // ---- fused per kt: exp -> pack -> PV for both tiles (shared V) ----
#pragma unroll
            for (int kt = 0; kt < 4; ++kt) {
                const bool do0 = act0 && !(diag0 && kt > lw);
                const bool do1 = !(diag1 && kt > lw);
                if (!do0 && !do1) continue;
                uint32_t pha0[4], pla0[4], pha1[4], pla1[4];
#pragma unroll
                for (int h = 0; h < 2; ++h) {
                    const int n = 2 * kt + h;
                    if (do0) {
                        float p0 = __expf(s0[n][0]);
                        float p1 = __expf(s0[n][1]);
                        float p2 = __expf(s0[n][2]);
                        float p3 = __expf(s0[n][3]);
                        if (diag0) {
                            const int col = j0 + 8 * n + 2 * tg;
                            if (col     > row0)     p0 = 0.f;
                            if (col + 1 > row0)     p1 = 0.f;
                            if (col     > row0 + 8) p2 = 0.f;
                            if (col + 1 > row0 + 8) p3 = 0.f;
                        }
                        ellA0 += p0 + p1;
                        ellB0 += p2 + p3;
                        uint32_t h01, l01, h23, l23;
                        split_pair(p0, p1, h01, l01);
                        split_pair(p2, p3, h23, l23);
                        if (h == 0) { pha0[0]=h01; pha0[1]=h23; pla0[0]=l01; pla0[1]=l23; }
                        else        { pha0[2]=h01; pha0[3]=h23; pla0[2]=l01; pla0[3]=l23; }
                    }
                    if (do1) {
                        float p0 = __expf(s1[n][0]);
                        float p1 = __expf(s1[n][1]);
                        float p2 = __expf(s1[n][2]);
                        float p3 = __expf(s1[n][3]);
                        if (diag1) {
                            const int col = j0 + 8 * n + 2 * tg;
                            if (col     > row1)     p0 = 0.f;
                            if (col + 1 > row1)     p1 = 0.f;
                            if (col     > row1 + 8) p2 = 0.f;
                            if (col + 1 > row1 + 8) p3 = 0.f;
                        }
                        ellA1 += p0 + p1;
                        ellB1 += p2 + p3;
                        uint32_t h01, l01, h23, l23;
                        split_pair(p0, p1, h01, l01);
                        split_pair(p2, p3, h23, l23);
                        if (h == 0) { pha1[0]=h01; pha1[1]=h23; pla1[0]=l01; pla1[1]=l23; }
                        else        { pha1[2]=h01; pha1[3]=h23; pla1[2]=l01; pla1[3]=l23; }
                    }
                }
#pragma unroll
                for (int p = 0; p < 4; ++p) {
                    uint32_t h0, h1, h2, h3, l0, l1, l2, l3;
                    ldsm_x4(h0, h1, h2, h3, Vh + p * 16 * RS + kt * 32 + boff);
                    ldsm_x4(l0, l1, l2, l3, Vl + p * 16 * RS + kt * 32 + boff);
                    if (do0) {
                        mma_bf16(o0[2*p],   pha0, h0, h1);
                        mma_bf16(o0[2*p],   pla0, h0, h1);
                        mma_bf16(o0[2*p],   pha0, l0, l1);
                        mma_bf16(o0[2*p+1], pha0, h2, h3);
                        mma_bf16(o0[2*p+1], pla0, h2, h3);
                        mma_bf16(o0[2*p+1], pha0, l2, l3);
                    }
                    if (do1) {
                        mma_bf16(o1[2*p],   pha1, h0, h1);
                        mma_bf16(o1[2*p],   pla1, h0, h1);
                        mma_bf16(o1[2*p],   pha1, l0, l1);
                        mma_bf16(o1[2*p+1], pha1, h2, h3);
                        mma_bf16(o1[2*p+1], pla1, h2, h3);
                        mma_bf16(o1[2*p+1], pha1, l2, l3);
                    }
                }
            }

            __syncthreads();   // V consumed by all warps
            if (more) stageV(jt + 1);
        }

        // ---- epilogue: RED partial (O, ell) for both m-tiles ----
        ellA0 += __shfl_xor_sync(0xffffffffu, ellA0, 1);
        ellA0 += __shfl_xor_sync(0xffffffffu, ellA0, 2);
        ellB0 += __shfl_xor_sync(0xffffffffu, ellB0, 1);
        ellB0 += __shfl_xor_sync(0xffffffffu, ellB0, 2);
        ellA1 += __shfl_xor_sync(0xffffffffu, ellA1, 1);
        ellA1 += __shfl_xor_sync(0xffffffffu, ellA1, 2);
        ellB1 += __shfl_xor_sync(0xffffffffu, ellB1, 1);
        ellB1 += __shfl_xor_sync(0xffffffffu, ellB1, 2);
        if (tg == 0) {
            atomicAdd(&g_ell[b * 4096 + row0],     ellA0);
            atomicAdd(&g_ell[b * 4096 + row0 + 8], ellB0);
            atomicAdd(&g_ell[b * 4096 + row1],     ellA1);
            atomicAdd(&g_ell[b * 4096 + row1 + 8], ellB1);
        }
        float* OA0 = g_O + (size_t)(b * 4096 + row0) * 64;
        float* OB0 = OA0 + 8 * 64;
        float* OA1 = g_O + (size_t)(b * 4096 + row1) * 64;
        float* OB1 = OA1 + 8 * 64;
#pragma unroll
        for (int n = 0; n < 8; ++n) {
            const int col = 8 * n + 2 * tg;
            redg_v2(OA0 + col, o0[n][0], o0[n][1]);
            redg_v2(OB0 + col, o0[n][2], o0[n][3]);
            redg_v2(OA1 + col, o1[n][0], o1[n][1]);
            redg_v2(OB1 + col, o1[n][2], o1[n][3]);
        }
        __syncthreads();   // all smem reads done before next chunk restages
    }
}

// ============================================================================
// Divide: out = O / ell
// ============================================================================
__global__ __launch_bounds__(256) void divide_kernel(float* __restrict__ out)
{
    const size_t tid0 = (size_t)blockIdx.x * 256 + threadIdx.x;
    const size_t stride = (size_t)gridDim.x * 256;
    const size_t N = (size_t)MROWS * HH / 4;
    for (size_t u = tid0; u < N; u += stride) {
        const size_t m = u >> 4;
        const float inv = 1.0f / g_ell[m];
        float4 v = ((const float4*)g_O)[u];
        v.x *= inv; v.y *= inv; v.z *= inv; v.w *= inv;
        ((float4*)out)[u] = v;
    }
}

// ============================================================================
extern "C" void kernel_launch(void* const* d_in, const int* in_sizes, int n_in,
                              void* d_out, int out_size)
{
    const float* x  = (const float*)d_in[0];
    const float* Wq = (const float*)d_in[1];
    const float* bq = (const float*)d_in[2];
    const float* Wk = (const float*)d_in[3];
    const float* bk = (const float*)d_in[4];
    const float* Wv = (const float*)d_in[5];
    const float* bv = (const float*)d_in[6];
    float* out = (float*)d_out;

    cudaFuncSetAttribute(proj_kernel, cudaFuncAttributeMaxDynamicSharedMemorySize, PROJ_SMEM);
    cudaFuncSetAttribute(attn_kernel, cudaFuncAttributeMaxDynamicSharedMemorySize, ATTN_SMEM);

    // 6 launches/replay; captured launch #16 -> position 4 = attn_kernel.
    convert_kernel<<<1024, 256>>>(x, Wq, Wk, Wv);
    proj_kernel<<<dim3(128, 3), 256, PROJ_SMEM>>>(bq, bk, bv);
    dummy_kernel<<<1, 32>>>();
    attn_kernel<<<296, 128, ATTN_SMEM>>>();
    divide_kernel<<<1024, 256>>>(out);
    dummy_kernel<<<1, 32>>>();
}

// round 15
// speedup vs baseline: 1.0738x; 1.0738x over previous
#include <cuda_runtime.h>
#include <cuda_bf16.h>
#include <cstdint>

#define BB 4
#define TT 4096
#define DIN 1024
#define HH 64
#define MROWS (BB*TT)

// bf16 hi/lo split scratch
__device__ __nv_bfloat16 g_qh[(size_t)MROWS*HH], g_ql[(size_t)MROWS*HH];
__device__ __nv_bfloat16 g_kh[(size_t)MROWS*HH], g_kl[(size_t)MROWS*HH];
__device__ __nv_bfloat16 g_vth[(size_t)MROWS*HH], g_vtl[(size_t)MROWS*HH]; // [b][h][t]
// pre-converted inputs
__device__ __nv_bfloat16 g_xh[(size_t)MROWS*DIN], g_xl[(size_t)MROWS*DIN];
__device__ __nv_bfloat16 g_wh[3*HH*DIN], g_wl[3*HH*DIN];
// attention accumulators (fp32)
__device__ float g_O[(size_t)MROWS*HH];
__device__ float g_ell[MROWS];

// ---------------- helpers ----------------
__device__ __forceinline__ void mma_bf16(float* d, const uint32_t* a,
                                         uint32_t b0, uint32_t b1) {
    asm volatile(
        "mma.sync.aligned.m16n8k16.row.col.f32.bf16.bf16.f32 "
        "{%0,%1,%2,%3}, {%4,%5,%6,%7}, {%8,%9}, {%0,%1,%2,%3};"
        : "+f"(d[0]), "+f"(d[1]), "+f"(d[2]), "+f"(d[3])
        : "r"(a[0]), "r"(a[1]), "r"(a[2]), "r"(a[3]), "r"(b0), "r"(b1));
}

__device__ __forceinline__ void ldsm_x4(uint32_t& r0, uint32_t& r1,
                                        uint32_t& r2, uint32_t& r3, uint32_t a) {
    asm volatile("ldmatrix.sync.aligned.m8n8.x4.shared.b16 {%0,%1,%2,%3}, [%4];"
                 : "=r"(r0), "=r"(r1), "=r"(r2), "=r"(r3) : "r"(a));
}

__device__ __forceinline__ void split_pair(float x, float y,
                                           uint32_t& h, uint32_t& l) {
    __nv_bfloat162 hv = __floats2bfloat162_rn(x, y);
    float hx = __bfloat162float(hv.x);
    float hy = __bfloat162float(hv.y);
    __nv_bfloat162 lv = __floats2bfloat162_rn(x - hx, y - hy);
    h = *reinterpret_cast<uint32_t*>(&hv);
    l = *reinterpret_cast<uint32_t*>(&lv);
}

__device__ __forceinline__ uint32_t smem_u32(const void* p) {
    uint32_t a;
    asm("{ .reg .u64 t; cvta.to.shared.u64 t, %1; cvt.u32.u64 %0, t; }"
        : "=r"(a) : "l"(p));
    return a;
}

__device__ __forceinline__ void cpa16(uint32_t dst, const void* src) {
    asm volatile("cp.async.cg.shared.global [%0], [%1], 16;"
                 :: "r"(dst), "l"(src) : "memory");
}
#define CPA_COMMIT() asm volatile("cp.async.commit_group;" ::: "memory")
#define CPA_WAIT(N)  asm volatile("cp.async.wait_group %0;" :: "n"(N) : "memory")

__device__ __forceinline__ void redg_v2(float* p, float a, float b) {
    asm volatile("red.global.add.v2.f32 [%0], {%1, %2};"
                 :: "l"(p), "f"(a), "f"(b) : "memory");
}

#define RS 144   // smem row stride bytes

// ============================================================================
// Pre-convert + zero accumulators
// ============================================================================
__global__ __launch_bounds__(256) void convert_kernel(
    const float* __restrict__ x,
    const float* __restrict__ Wq, const float* __restrict__ Wk,
    const float* __restrict__ Wv)
{
    const size_t tid0 = (size_t)blockIdx.x * 256 + threadIdx.x;
    const size_t stride = (size_t)gridDim.x * 256;
    const size_t NX = (size_t)MROWS * DIN / 4;
    for (size_t t = tid0; t < NX; t += stride) {
        float4 v = ((const float4*)x)[t];
        uint32_t h0, l0, h1, l1;
        split_pair(v.x, v.y, h0, l0);
        split_pair(v.z, v.w, h1, l1);
        ((uint2*)g_xh)[t] = make_uint2(h0, h1);
        ((uint2*)g_xl)[t] = make_uint2(l0, l1);
    }
    const size_t NW = (size_t)HH * DIN / 4;
    for (size_t t = tid0; t < 3 * NW; t += stride) {
        const int set = (int)(t / NW);
        const size_t o = t - (size_t)set * NW;
        const float* W = (set == 0) ? Wq : (set == 1) ? Wk : Wv;
        float4 v = ((const float4*)W)[o];
        uint32_t h0, l0, h1, l1;
        split_pair(v.x, v.y, h0, l0);
        split_pair(v.z, v.w, h1, l1);
        ((uint2*)g_wh)[t] = make_uint2(h0, h1);
        ((uint2*)g_wl)[t] = make_uint2(l0, l1);
    }
    const float4 z4 = make_float4(0.f, 0.f, 0.f, 0.f);
    const size_t NO = (size_t)MROWS * HH / 4;
    for (size_t t = tid0; t < NO; t += stride) ((float4*)g_O)[t] = z4;
    for (size_t t = tid0; t < MROWS / 4; t += stride) ((float4*)g_ell)[t] = z4;
}

// ============================================================================
// Projection: grid=(128,3), 256 thr, 2 CTAs/SM, cp.async double buffer + ldsm.
// ============================================================================
#define P_XH 0
#define P_XL (128*RS)
#define P_WH (256*RS)
#define P_WL (256*RS + 64*RS)
#define PBUF (384*RS)
#define PROJ_SMEM (2*PBUF)

__global__ __launch_bounds__(256, 2) void proj_kernel(
    const float* __restrict__ bq, const float* __restrict__ bk,
    const float* __restrict__ bv)
{
    extern __shared__ char smp[];
    __shared__ float s_bias[64];
    const uint32_t sbase = smem_u32(smp);

    const int tid = threadIdx.x;
    const int wid = tid >> 5, lane = tid & 31;
    const int g = lane >> 2, tg = lane & 3;
    const int m0 = blockIdx.x * 128;
    const int my = blockIdx.y;

    const float* bias = (my == 0) ? bq : (my == 1) ? bk : bv;
    if (tid < 64) s_bias[tid] = bias[tid];

    const size_t wset = (size_t)my * HH * DIN;

    auto stage = [&](int kc, int bi) {
        const int k0 = kc * 64;
        const uint32_t bb = sbase + bi * PBUF;
#pragma unroll
        for (int u = tid; u < 3072; u += 256) {
            uint32_t dst; const void* src;
            if (u < 2048) {
                const int comp = u >> 10;
                const int idx = u & 1023;
                const int r = idx >> 3, c8 = idx & 7;
                const __nv_bfloat16* gsrc = comp ? g_xl : g_xh;
                src = gsrc + (size_t)(m0 + r) * DIN + k0 + c8 * 8;
                dst = bb + (comp ? P_XL : P_XH) + r * RS + c8 * 16;
            } else {
                const int comp = (u - 2048) >> 9;
                const int idx = (u - 2048) & 511;
                const int r = idx >> 3, c8 = idx & 7;
                const __nv_bfloat16* gsrc = comp ? g_wl : g_wh;
                src = gsrc + wset + (size_t)r * DIN + k0 + c8 * 8;
                dst = bb + (comp ? P_WL : P_WH) + r * RS + c8 * 16;
            }
            cpa16(dst, src);
        }
        CPA_COMMIT();
    };

    const uint32_t aoff = (lane & 7) * RS + ((lane >> 3) & 1) * 8 * RS
                        + ((lane >> 4) & 1) * 16;
    const uint32_t boff = (lane & 7) * RS + ((lane >> 4) & 1) * 8 * RS
                        + ((lane >> 3) & 1) * 16;

    float acc[8][4];
#pragma unroll
    for (int n = 0; n < 8; ++n)
#pragma unroll
        for (int q = 0; q < 4; ++q) acc[n][q] = 0.f;

    stage(0, 0);
    for (int kc = 0; kc < 16; ++kc) {
        CPA_WAIT(0);
        __syncthreads();
        if (kc < 15) stage(kc + 1, (kc + 1) & 1);

        const uint32_t bb = sbase + (kc & 1) * PBUF;
        const uint32_t Xh = bb + P_XH, Xl = bb + P_XL;
        const uint32_t Wh = bb + P_WH, Wl = bb + P_WL;
        const int ra = wid * 16;

#pragma unroll
        for (int ks = 0; ks < 4; ++ks) {
            uint32_t ah[4], al[4];
            ldsm_x4(ah[0], ah[1], ah[2], ah[3], Xh + ra * RS + ks * 32 + aoff);
            ldsm_x4(al[0], al[1], al[2], al[3], Xl + ra * RS + ks * 32 + aoff);
#pragma unroll
            for (int p = 0; p < 4; ++p) {
                uint32_t h0, h1, h2, h3, l0, l1, l2, l3;
                ldsm_x4(h0, h1, h2, h3, Wh + p * 16 * RS + ks * 32 + boff);
                ldsm_x4(l0, l1, l2, l3, Wl + p * 16 * RS + ks * 32 + boff);
                mma_bf16(acc[2*p],   ah, h0, h1);
                mma_bf16(acc[2*p],   al, h0, h1);
                mma_bf16(acc[2*p],   ah, l0, l1);
                mma_bf16(acc[2*p+1], ah, h2, h3);
                mma_bf16(acc[2*p+1], al, h2, h3);
                mma_bf16(acc[2*p+1], ah, l2, l3);
            }
        }
        __syncthreads();
    }

    // epilogue
    const int rA = m0 + wid * 16 + g;
    const int rB = rA + 8;
#pragma unroll
    for (int n = 0; n < 8; ++n) {
        const int col = 8 * n + 2 * tg;
        float v0 = acc[n][0] + s_bias[col];
        float v1 = acc[n][1] + s_bias[col + 1];
        float v2 = acc[n][2] + s_bias[col];
        float v3 = acc[n][3] + s_bias[col + 1];
        if (my < 2) {
            uint32_t h01, l01, h23, l23;
            split_pair(v0, v1, h01, l01);
            split_pair(v2, v3, h23, l23);
            __nv_bfloat16* oh = (my == 0) ? g_qh : g_kh;
            __nv_bfloat16* ol = (my == 0) ? g_ql : g_kl;
            *(uint32_t*)(oh + (size_t)rA * 64 + col) = h01;
            *(uint32_t*)(ol + (size_t)rA * 64 + col) = l01;
            *(uint32_t*)(oh + (size_t)rB * 64 + col) = h23;
            *(uint32_t*)(ol + (size_t)rB * 64 + col) = l23;
        } else {
            const int bA = rA >> 12, tA = rA & 4095;
            const int bB = rB >> 12, tB = rB & 4095;
            __nv_bfloat16 h;
            h = __float2bfloat16_rn(v0);
            g_vth[(size_t)(bA*64 + col  )*4096 + tA] = h;
            g_vtl[(size_t)(bA*64 + col  )*4096 + tA] = __float2bfloat16_rn(v0 - __bfloat162float(h));
            h = __float2bfloat16_rn(v1);
            g_vth[(size_t)(bA*64 + col+1)*4096 + tA] = h;
            g_vtl[(size_t)(bA*64 + col+1)*4096 + tA] = __float2bfloat16_rn(v1 - __bfloat162float(h));
            h = __float2bfloat16_rn(v2);
            g_vth[(size_t)(bB*64 + col  )*4096 + tB] = h;
            g_vtl[(size_t)(bB*64 + col  )*4096 + tB] = __float2bfloat16_rn(v2 - __bfloat162float(h));
            h = __float2bfloat16_rn(v3);
            g_vth[(size_t)(bB*64 + col+1)*4096 + tB] = h;
            g_vtl[(size_t)(bB*64 + col+1)*4096 + tB] = __float2bfloat16_rn(v3 - __bfloat162float(h));
        }
    }
}

// ============================================================================
// Attention (round-9 structure + diagonal kt-skip):
// chunk = 8 j-tiles, grid = 4 x 288, CTA = 128 thr, 4 CTAs/SM.
// Fused exp->PV per kt; split-phase Q/V prefetch; K resident.
// Linear softmax; RED accumulate; divide after.
// ============================================================================
#define AK   (2*64*RS)                  // 18432: Kh,Kl
#define AQ   (2*64*RS)                  // Qh,Ql
#define AV   (2*64*RS)                  // Vh,Vl
#define ATTN_SMEM (AK + AQ + AV)        // 55296

__global__ __launch_bounds__(128, 4) void attn_kernel()
{
    extern __shared__ char smp[];
    const uint32_t sbase = smem_u32(smp);
    const int tid = threadIdx.x;
    const int lw  = tid >> 5;
    const int lane = tid & 31;
    const int g  = lane >> 2, tg = lane & 3;

    const int b   = blockIdx.x & 3;
    const int cid = 287 - (blockIdx.x >> 2);
    const int t = (cid >= 224) ? 7 : (cid >= 168) ? 6 : (cid >= 120) ? 5 :
                  (cid >= 80)  ? 4 : (cid >= 48)  ? 3 : (cid >= 24)  ? 2 :
                  (cid >= 8)   ? 1 : 0;
    const int off = cid - 4 * t * (t + 1);
    const int rb  = 8 * t + off / (t + 1);
    const int jc  = off % (t + 1);
    const int jt0 = jc * 8;
    const int jt1 = min(jt0 + 8, rb + 1);
    const int i0  = rb * 64;

    const uint32_t Kb = sbase;            // Kh at 0, Kl at +64*RS
    const uint32_t Qb = sbase + AK;       // Qh, Ql
    const uint32_t Vb = Qb + 2 * 64 * RS; // Vh, Vl

    // group 0: K tile
#pragma unroll
    for (int i = tid; i < 1024; i += 128) {
        const int comp = i >> 9;
        const int idx = i & 511;
        const int r = idx >> 3, c8 = idx & 7;
        const __nv_bfloat16* gsrc = comp ? g_kl : g_kh;
        cpa16(Kb + comp * (64 * RS) + r * RS + c8 * 16,
              gsrc + (size_t)(b * 4096 + i0 + r) * 64 + c8 * 8);
    }
    CPA_COMMIT();

    auto stageQ = [&](int jt) {
        const int j0 = jt * 64;
#pragma unroll
        for (int i = tid; i < 1024; i += 128) {
            const int comp = i >> 9;
            const int idx = i & 511;
            const int r = idx >> 3, c8 = idx & 7;
            const __nv_bfloat16* gsrc = comp ? g_ql : g_qh;
            cpa16(Qb + comp * (64 * RS) + r * RS + c8 * 16,
                  gsrc + (size_t)(b * 4096 + j0 + r) * 64 + c8 * 8);
        }
        CPA_COMMIT();
    };
    auto stageV = [&](int jt) {
        const int j0 = jt * 64;
#pragma unroll
        for (int i = tid; i < 1024; i += 128) {
            const int comp = i >> 9;
            const int idx = i & 511;
            const int r = idx >> 3, c8 = idx & 7;
            const __nv_bfloat16* gsrc = comp ? g_vtl : g_vth;
            cpa16(Vb + comp * (64 * RS) + r * RS + c8 * 16,
                  gsrc + (size_t)(b * 64 + r) * 4096 + j0 + c8 * 8);
        }
        CPA_COMMIT();
    };

    const uint32_t aoff = (lane & 7) * RS + ((lane >> 3) & 1) * 8 * RS
                        + ((lane >> 4) & 1) * 16;
    const uint32_t boff = (lane & 7) * RS + ((lane >> 4) & 1) * 8 * RS
                        + ((lane >> 3) & 1) * 16;
    const int rowA = i0 + lw * 16 + g;

    float o[8][4];
#pragma unroll
    for (int n = 0; n < 8; ++n)
#pragma unroll
        for (int q = 0; q < 4; ++q) o[n][q] = 0.f;
    float ellA = 0.f, ellB = 0.f;

    stageQ(jt0);     // group 1
    stageV(jt0);     // group 2

    for (int jt = jt0; jt < jt1; ++jt) {
        const int j0 = jt * 64;
        const bool more = (jt + 1 < jt1);

        // wait for K (first iter) + Q(jt); V(jt) may still be in flight
        CPA_WAIT(1);
        __syncthreads();

        const uint32_t Qh = Qb, Ql = Qb + 64 * RS;
        const uint32_t Vh = Vb, Vl = Vb + 64 * RS;

        // ---- S = K . Q^T ----
        float s[8][4];
#pragma unroll
        for (int n = 0; n < 8; ++n)
#pragma unroll
            for (int q = 0; q < 4; ++q) s[n][q] = 0.f;

#pragma unroll
        for (int ks = 0; ks < 4; ++ks) {
            uint32_t kh[4], kl[4];
            ldsm_x4(kh[0], kh[1], kh[2], kh[3],
                    Kb + (lw * 16) * RS + ks * 32 + aoff);
            ldsm_x4(kl[0], kl[1], kl[2], kl[3],
                    Kb + 64 * RS + (lw * 16) * RS + ks * 32 + aoff);
#pragma unroll
            for (int p = 0; p < 4; ++p) {
                uint32_t h0, h1, h2, h3, l0, l1, l2, l3;
                ldsm_x4(h0, h1, h2, h3, Qh + p * 16 * RS + ks * 32 + boff);
                ldsm_x4(l0, l1, l2, l3, Ql + p * 16 * RS + ks * 32 + boff);
                mma_bf16(s[2*p],   kh, h0, h1);
                mma_bf16(s[2*p],   kl, h0, h1);
                mma_bf16(s[2*p],   kh, l0, l1);
                mma_bf16(s[2*p+1], kh, h2, h3);
                mma_bf16(s[2*p+1], kl, h2, h3);
                mma_bf16(s[2*p+1], kh, l2, l3);
            }
        }

        // Q consumed -> prefetch Q(jt+1) into the same buffer
        __syncthreads();
        if (more) stageQ(jt + 1);

        // wait for V(jt); Q(jt+1) (if any) stays in flight
        if (more) { CPA_WAIT(1); } else { CPA_WAIT(0); }
        __syncthreads();

        // ---- fused per kt: exp(s) -> pack -> O += P_kt . V_kt ----
        const bool diag = (jt == rb);
#pragma unroll
        for (int kt = 0; kt < 4; ++kt) {
            if (diag && kt > lw) break;   // all-masked kt blocks (verified)
            uint32_t pha[4], pla[4];
#pragma unroll
            for (int h = 0; h < 2; ++h) {
                const int n = 2 * kt + h;
                float p0 = __expf(s[n][0]);
                float p1 = __expf(s[n][1]);
                float p2 = __expf(s[n][2]);
                float p3 = __expf(s[n][3]);
                if (diag) {
                    const int col = j0 + 8 * n + 2 * tg;
                    if (col     > rowA)     p0 = 0.f;
                    if (col + 1 > rowA)     p1 = 0.f;
                    if (col     > rowA + 8) p2 = 0.f;
                    if (col + 1 > rowA + 8) p3 = 0.f;
                }
                ellA += p0 + p1;
                ellB += p2 + p3;
                uint32_t h01, l01, h23, l23;
                split_pair(p0, p1, h01, l01);
                split_pair(p2, p3, h23, l23);
                if (h == 0) {
                    pha[0] = h01; pha[1] = h23;
                    pla[0] = l01; pla[1] = l23;
                } else {
                    pha[2] = h01; pha[3] = h23;
                    pla[2] = l01; pla[3] = l23;
                }
            }
#pragma unroll
            for (int p = 0; p < 4; ++p) {
                uint32_t h0, h1, h2, h3, l0, l1, l2, l3;
                ldsm_x4(h0, h1, h2, h3, Vh + p * 16 * RS + kt * 32 + boff);
                ldsm_x4(l0, l1, l2, l3, Vl + p * 16 * RS + kt * 32 + boff);
                mma_bf16(o[2*p],   pha, h0, h1);
                mma_bf16(o[2*p],   pla, h0, h1);
                mma_bf16(o[2*p],   pha, l0, l1);
                mma_bf16(o[2*p+1], pha, h2, h3);
                mma_bf16(o[2*p+1], pla, h2, h3);
                mma_bf16(o[2*p+1], pha, l2, l3);
            }
        }

        __syncthreads();   // V consumed by all warps
        if (more) stageV(jt + 1);
    }

    // ---- epilogue: vector red accumulate O, scalar ell ----
    ellA += __shfl_xor_sync(0xffffffffu, ellA, 1);
    ellA += __shfl_xor_sync(0xffffffffu, ellA, 2);
    ellB += __shfl_xor_sync(0xffffffffu, ellB, 1);
    ellB += __shfl_xor_sync(0xffffffffu, ellB, 2);
    if (tg == 0) {
        atomicAdd(&g_ell[b * 4096 + rowA],     ellA);
        atomicAdd(&g_ell[b * 4096 + rowA + 8], ellB);
    }
    float* OA = g_O + (size_t)(b * 4096 + rowA) * 64;
    float* OB = OA + 8 * 64;
#pragma unroll
    for (int n = 0; n < 8; ++n) {
        const int col = 8 * n + 2 * tg;
        redg_v2(OA + col, o[n][0], o[n][1]);
        redg_v2(OB + col, o[n][2], o[n][3]);
    }
}

// ============================================================================
// Divide: out = O / ell
// ============================================================================
__global__ __launch_bounds__(256) void divide_kernel(float* __restrict__ out)
{
    const size_t tid0 = (size_t)blockIdx.x * 256 + threadIdx.x;
    const size_t stride = (size_t)gridDim.x * 256;
    const size_t N = (size_t)MROWS * HH / 4;
    for (size_t u = tid0; u < N; u += stride) {
        const size_t m = u >> 4;
        const float inv = 1.0f / g_ell[m];
        float4 v = ((const float4*)g_O)[u];
        v.x *= inv; v.y *= inv; v.z *= inv; v.w *= inv;
        ((float4*)out)[u] = v;
    }
}

// ============================================================================
extern "C" void kernel_launch(void* const* d_in, const int* in_sizes, int n_in,
                              void* d_out, int out_size)
{
    const float* x  = (const float*)d_in[0];
    const float* Wq = (const float*)d_in[1];
    const float* bq = (const float*)d_in[2];
    const float* Wk = (const float*)d_in[3];
    const float* bk = (const float*)d_in[4];
    const float* Wv = (const float*)d_in[5];
    const float* bv = (const float*)d_in[6];
    float* out = (float*)d_out;

    cudaFuncSetAttribute(proj_kernel, cudaFuncAttributeMaxDynamicSharedMemorySize, PROJ_SMEM);
    cudaFuncSetAttribute(attn_kernel, cudaFuncAttributeMaxDynamicSharedMemorySize, ATTN_SMEM);

    convert_kernel<<<1024, 256>>>(x, Wq, Wk, Wv);
    proj_kernel<<<dim3(128, 3), 256, PROJ_SMEM>>>(bq, bk, bv);
    attn_kernel<<<4 * 288, 128, ATTN_SMEM>>>();
    divide_kernel<<<1024, 256>>>(out);
}

// round 17
// speedup vs baseline: 1.2762x; 1.1885x over previous
#include <cuda_runtime.h>
#include <cuda_bf16.h>
#include <cstdint>

#define BB 4
#define TT 4096
#define DIN 1024
#define HH 64
#define MROWS (BB*TT)

// bf16 hi/lo split scratch (proj outputs)
__device__ __nv_bfloat16 g_qh[(size_t)MROWS*HH], g_ql[(size_t)MROWS*HH];
__device__ __nv_bfloat16 g_kh[(size_t)MROWS*HH], g_kl[(size_t)MROWS*HH];
__device__ __nv_bfloat16 g_vth[(size_t)MROWS*HH], g_vtl[(size_t)MROWS*HH]; // [b][h][t]
// pre-converted weights only (X converted inside proj now)
__device__ __nv_bfloat16 g_wh[3*HH*DIN], g_wl[3*HH*DIN];   // [set*64+n][k]
// attention accumulators (fp32)
__device__ float g_O[(size_t)MROWS*HH];
__device__ float g_ell[MROWS];

// ---------------- helpers ----------------
__device__ __forceinline__ void mma_bf16(float* d, const uint32_t* a,
                                         uint32_t b0, uint32_t b1) {
    asm volatile(
        "mma.sync.aligned.m16n8k16.row.col.f32.bf16.bf16.f32 "
        "{%0,%1,%2,%3}, {%4,%5,%6,%7}, {%8,%9}, {%0,%1,%2,%3};"
        : "+f"(d[0]), "+f"(d[1]), "+f"(d[2]), "+f"(d[3])
        : "r"(a[0]), "r"(a[1]), "r"(a[2]), "r"(a[3]), "r"(b0), "r"(b1));
}

__device__ __forceinline__ void ldsm_x4(uint32_t& r0, uint32_t& r1,
                                        uint32_t& r2, uint32_t& r3, uint32_t a) {
    asm volatile("ldmatrix.sync.aligned.m8n8.x4.shared.b16 {%0,%1,%2,%3}, [%4];"
                 : "=r"(r0), "=r"(r1), "=r"(r2), "=r"(r3) : "r"(a));
}

__device__ __forceinline__ void split_pair(float x, float y,
                                           uint32_t& h, uint32_t& l) {
    __nv_bfloat162 hv = __floats2bfloat162_rn(x, y);
    float hx = __bfloat162float(hv.x);
    float hy = __bfloat162float(hv.y);
    __nv_bfloat162 lv = __floats2bfloat162_rn(x - hx, y - hy);
    h = *reinterpret_cast<uint32_t*>(&hv);
    l = *reinterpret_cast<uint32_t*>(&lv);
}

__device__ __forceinline__ uint32_t smem_u32(const void* p) {
    uint32_t a;
    asm("{ .reg .u64 t; cvta.to.shared.u64 t, %1; cvt.u32.u64 %0, t; }"
        : "=r"(a) : "l"(p));
    return a;
}

__device__ __forceinline__ void cpa16(uint32_t dst, const void* src) {
    asm volatile("cp.async.cg.shared.global [%0], [%1], 16;"
                 :: "r"(dst), "l"(src) : "memory");
}
#define CPA_COMMIT() asm volatile("cp.async.commit_group;" ::: "memory")
#define CPA_WAIT(N)  asm volatile("cp.async.wait_group %0;" :: "n"(N) : "memory")

__device__ __forceinline__ void redg_v2(float* p, float a, float b) {
    asm volatile("red.global.add.v2.f32 [%0], {%1, %2};"
                 :: "l"(p), "f"(a), "f"(b) : "memory");
}

#define RS 144   // smem row stride bytes

// ============================================================================
// Convert: W -> (g_wh, g_wl) + zero accumulators.  (X handled inside proj.)
// ============================================================================
__global__ __launch_bounds__(256) void convert_kernel(
    const float* __restrict__ Wq, const float* __restrict__ Wk,
    const float* __restrict__ Wv)
{
    const size_t tid0 = (size_t)blockIdx.x * 256 + threadIdx.x;
    const size_t stride = (size_t)gridDim.x * 256;
    const size_t NW = (size_t)HH * DIN / 4;   // per set, float4 units
    for (size_t t = tid0; t < 3 * NW; t += stride) {
        const int set = (int)(t / NW);
        const size_t o = t - (size_t)set * NW;
        const float* W = (set == 0) ? Wq : (set == 1) ? Wk : Wv;
        float4 v = ((const float4*)W)[o];
        uint32_t h0, l0, h1, l1;
        split_pair(v.x, v.y, h0, l0);
        split_pair(v.z, v.w, h1, l1);
        ((uint2*)g_wh)[t] = make_uint2(h0, h1);
        ((uint2*)g_wl)[t] = make_uint2(l0, l1);
    }
    const float4 z4 = make_float4(0.f, 0.f, 0.f, 0.f);
    const size_t NO = (size_t)MROWS * HH / 4;
    for (size_t t = tid0; t < NO; t += stride) ((float4*)g_O)[t] = z4;
    for (size_t t = tid0; t < MROWS / 4; t += stride) ((float4*)g_ell)[t] = z4;
}

// ============================================================================
// Fused projection: grid = 128 CTAs (1/SM), 256 thr. Each CTA: 128 rows x
// N=192 (Wq|Wk|Wv). X read as float ONCE, split in registers (LDG of chunk
// kc+1 issued before chunk kc's MMA -> latency hidden). W pre-split,
// cp.async double-buffered.
// ============================================================================
#define PF_XH 0
#define PF_XL (128*RS)
#define PF_WH (256*RS)
#define PF_WL (256*RS + 192*RS)
#define PFBUF (640*RS)              // 92160 per buffer
#define PROJ_SMEM (2*PFBUF)         // 184320 -> 1 CTA/SM

__global__ __launch_bounds__(256, 1) void proj_kernel(
    const float* __restrict__ x,
    const float* __restrict__ bq, const float* __restrict__ bk,
    const float* __restrict__ bv)
{
    extern __shared__ char smp[];
    __shared__ float s_bias[192];
    const uint32_t sbase = smem_u32(smp);

    const int tid = threadIdx.x;
    const int wid = tid >> 5, lane = tid & 31;
    const int g = lane >> 2, tg = lane & 3;
    const int m0 = blockIdx.x * 128;

    if (tid < 192)
        s_bias[tid] = (tid < 64) ? bq[tid] : (tid < 128) ? bk[tid - 64] : bv[tid - 128];

    // per-thread X float4 slots: idx = i*256+tid -> row idx>>4, col4 idx&15
    float4 xreg[8];
    auto ldgX = [&](int kc) {
        const int k0 = kc * 64;
#pragma unroll
        for (int i = 0; i < 8; ++i) {
            const int idx = i * 256 + tid;
            const int r = idx >> 4, c4 = idx & 15;
            xreg[i] = *(const float4*)(x + (size_t)(m0 + r) * DIN + k0 + c4 * 4);
        }
    };
    auto stsX = [&](int bi) {
        char* bb = smp + bi * PFBUF;
#pragma unroll
        for (int i = 0; i < 8; ++i) {
            const int idx = i * 256 + tid;
            const int r = idx >> 4, c4 = idx & 15;
            uint32_t h0, l0, h1, l1;
            split_pair(xreg[i].x, xreg[i].y, h0, l0);
            split_pair(xreg[i].z, xreg[i].w, h1, l1);
            *(uint2*)(bb + PF_XH + r * RS + c4 * 8) = make_uint2(h0, h1);
            *(uint2*)(bb + PF_XL + r * RS + c4 * 8) = make_uint2(l0, l1);
        }
    };
    auto stageW = [&](int kc, int bi) {
        const int k0 = kc * 64;
        const uint32_t bb = sbase + bi * PFBUF;
#pragma unroll
        for (int u = tid; u < 3072; u += 256) {
            const int comp = (u >= 1536);
            const int idx = u - comp * 1536;
            const int r = idx >> 3, c8 = idx & 7;   // r in 0..191
            const __nv_bfloat16* gsrc = comp ? g_wl : g_wh;
            cpa16(bb + (comp ? PF_WL : PF_WH) + r * RS + c8 * 16,
                  gsrc + (size_t)r * DIN + k0 + c8 * 8);
        }
        CPA_COMMIT();
    };

    const uint32_t aoff = (lane & 7) * RS + ((lane >> 3) & 1) * 8 * RS
                        + ((lane >> 4) & 1) * 16;
    const uint32_t boff = (lane & 7) * RS + ((lane >> 4) & 1) * 8 * RS
                        + ((lane >> 3) & 1) * 16;

    float acc[24][4];
#pragma unroll
    for (int n = 0; n < 24; ++n)
#pragma unroll
        for (int q = 0; q < 4; ++q) acc[n][q] = 0.f;

    // prologue
    ldgX(0);
    stageW(0, 0);
    stsX(0);

    for (int kc = 0; kc < 16; ++kc) {
        const bool more = (kc < 15);
        if (more) ldgX(kc + 1);          // LDG early; consumed after MMA
        CPA_WAIT(0);                     // W(kc) done
        __syncthreads();                 // X(kc) STS visible
        if (more) stageW(kc + 1, (kc + 1) & 1);

        const uint32_t bb = sbase + (kc & 1) * PFBUF;
        const uint32_t Xh = bb + PF_XH, Xl = bb + PF_XL;
        const uint32_t Wh = bb + PF_WH, Wl = bb + PF_WL;
        const int ra = wid * 16;

#pragma unroll
        for (int ks = 0; ks < 4; ++ks) {
            uint32_t ah[4], al[4];
            ldsm_x4(ah[0], ah[1], ah[2], ah[3], Xh + ra * RS + ks * 32 + aoff);
            ldsm_x4(al[0], al[1], al[2], al[3], Xl + ra * RS + ks * 32 + aoff);
#pragma unroll
            for (int p = 0; p < 12; ++p) {
                uint32_t h0, h1, h2, h3, l0, l1, l2, l3;
                ldsm_x4(h0, h1, h2, h3, Wh + p * 16 * RS + ks * 32 + boff);
                ldsm_x4(l0, l1, l2, l3, Wl + p * 16 * RS + ks * 32 + boff);
                mma_bf16(acc[2*p],   ah, h0, h1);
                mma_bf16(acc[2*p],   al, h0, h1);
                mma_bf16(acc[2*p],   ah, l0, l1);
                mma_bf16(acc[2*p+1], ah, h2, h3);
                mma_bf16(acc[2*p+1], al, h2, h3);
                mma_bf16(acc[2*p+1], ah, l2, l3);
            }
        }

        if (more) stsX((kc + 1) & 1);    // convert+store next X chunk
        __syncthreads();                 // MMA reads done; buffers reusable
    }

    // epilogue: 24 n-blocks -> set = col192/64
    const int rA = m0 + wid * 16 + g;
    const int rB = rA + 8;
#pragma unroll
    for (int n = 0; n < 24; ++n) {
        const int col192 = 8 * n + 2 * tg;
        const int set = col192 >> 6;
        const int col = col192 & 63;
        float v0 = acc[n][0] + s_bias[col192];
        float v1 = acc[n][1] + s_bias[col192 + 1];
        float v2 = acc[n][2] + s_bias[col192];
        float v3 = acc[n][3] + s_bias[col192 + 1];
        if (set < 2) {
            uint32_t h01, l01, h23, l23;
            split_pair(v0, v1, h01, l01);
            split_pair(v2, v3, h23, l23);
            __nv_bfloat16* oh = (set == 0) ? g_qh : g_kh;
            __nv_bfloat16* ol = (set == 0) ? g_ql : g_kl;
            *(uint32_t*)(oh + (size_t)rA * 64 + col) = h01;
            *(uint32_t*)(ol + (size_t)rA * 64 + col) = l01;
            *(uint32_t*)(oh + (size_t)rB * 64 + col) = h23;
            *(uint32_t*)(ol + (size_t)rB * 64 + col) = l23;
        } else {
            const int bA = rA >> 12, tA = rA & 4095;
            const int bB = rB >> 12, tB = rB & 4095;
            __nv_bfloat16 h;
            h = __float2bfloat16_rn(v0);
            g_vth[(size_t)(bA*64 + col  )*4096 + tA] = h;
            g_vtl[(size_t)(bA*64 + col  )*4096 + tA] = __float2bfloat16_rn(v0 - __bfloat162float(h));
            h = __float2bfloat16_rn(v1);
            g_vth[(size_t)(bA*64 + col+1)*4096 + tA] = h;
            g_vtl[(size_t)(bA*64 + col+1)*4096 + tA] = __float2bfloat16_rn(v1 - __bfloat162float(h));
            h = __float2bfloat16_rn(v2);
            g_vth[(size_t)(bB*64 + col  )*4096 + tB] = h;
            g_vtl[(size_t)(bB*64 + col  )*4096 + tB] = __float2bfloat16_rn(v2 - __bfloat162float(h));
            h = __float2bfloat16_rn(v3);
            g_vth[(size_t)(bB*64 + col+1)*4096 + tB] = h;
            g_vtl[(size_t)(bB*64 + col+1)*4096 + tB] = __float2bfloat16_rn(v3 - __bfloat162float(h));
        }
    }
}

// ============================================================================
// Attention (exact round-9 structure — best timed):
// chunk = 8 j-tiles, grid = 4 x 288, CTA = 128 thr, 4 CTAs/SM.
// Fused exp->PV per kt; split-phase Q/V prefetch; K resident.
// Linear softmax; RED accumulate; divide after.
// ============================================================================
#define AK   (2*64*RS)
#define AQ   (2*64*RS)
#define AV   (2*64*RS)
#define ATTN_SMEM (AK + AQ + AV)        // 55296

__global__ __launch_bounds__(128, 4) void attn_kernel()
{
    extern __shared__ char smp[];
    const uint32_t sbase = smem_u32(smp);
    const int tid = threadIdx.x;
    const int lw  = tid >> 5;
    const int lane = tid & 31;
    const int g  = lane >> 2, tg = lane & 3;

    const int b   = blockIdx.x & 3;
    const int cid = 287 - (blockIdx.x >> 2);
    const int t = (cid >= 224) ? 7 : (cid >= 168) ? 6 : (cid >= 120) ? 5 :
                  (cid >= 80)  ? 4 : (cid >= 48)  ? 3 : (cid >= 24)  ? 2 :
                  (cid >= 8)   ? 1 : 0;
    const int off = cid - 4 * t * (t + 1);
    const int rb  = 8 * t + off / (t + 1);
    const int jc  = off % (t + 1);
    const int jt0 = jc * 8;
    const int jt1 = min(jt0 + 8, rb + 1);
    const int i0  = rb * 64;

    const uint32_t Kb = sbase;
    const uint32_t Qb = sbase + AK;
    const uint32_t Vb = Qb + 2 * 64 * RS;

    // group 0: K tile
#pragma unroll
    for (int i = tid; i < 1024; i += 128) {
        const int comp = i >> 9;
        const int idx = i & 511;
        const int r = idx >> 3, c8 = idx & 7;
        const __nv_bfloat16* gsrc = comp ? g_kl : g_kh;
        cpa16(Kb + comp * (64 * RS) + r * RS + c8 * 16,
              gsrc + (size_t)(b * 4096 + i0 + r) * 64 + c8 * 8);
    }
    CPA_COMMIT();

    auto stageQ = [&](int jt) {
        const int j0 = jt * 64;
#pragma unroll
        for (int i = tid; i < 1024; i += 128) {
            const int comp = i >> 9;
            const int idx = i & 511;
            const int r = idx >> 3, c8 = idx & 7;
            const __nv_bfloat16* gsrc = comp ? g_ql : g_qh;
            cpa16(Qb + comp * (64 * RS) + r * RS + c8 * 16,
                  gsrc + (size_t)(b * 4096 + j0 + r) * 64 + c8 * 8);
        }
        CPA_COMMIT();
    };
    auto stageV = [&](int jt) {
        const int j0 = jt * 64;
#pragma unroll
        for (int i = tid; i < 1024; i += 128) {
            const int comp = i >> 9;
            const int idx = i & 511;
            const int r = idx >> 3, c8 = idx & 7;
            const __nv_bfloat16* gsrc = comp ? g_vtl : g_vth;
            cpa16(Vb + comp * (64 * RS) + r * RS + c8 * 16,
                  gsrc + (size_t)(b * 64 + r) * 4096 + j0 + c8 * 8);
        }
        CPA_COMMIT();
    };

    const uint32_t aoff = (lane & 7) * RS + ((lane >> 3) & 1) * 8 * RS
                        + ((lane >> 4) & 1) * 16;
    const uint32_t boff = (lane & 7) * RS + ((lane >> 4) & 1) * 8 * RS
                        + ((lane >> 3) & 1) * 16;
    const int rowA = i0 + lw * 16 + g;

    float o[8][4];
#pragma unroll
    for (int n = 0; n < 8; ++n)
#pragma unroll
        for (int q = 0; q < 4; ++q) o[n][q] = 0.f;
    float ellA = 0.f, ellB = 0.f;

    stageQ(jt0);
    stageV(jt0);

    for (int jt = jt0; jt < jt1; ++jt) {
        const int j0 = jt * 64;
        const bool more = (jt + 1 < jt1);

        CPA_WAIT(1);
        __syncthreads();

        const uint32_t Qh = Qb, Ql = Qb + 64 * RS;
        const uint32_t Vh = Vb, Vl = Vb + 64 * RS;

        // ---- S = K . Q^T ----
        float s[8][4];
#pragma unroll
        for (int n = 0; n < 8; ++n)
#pragma unroll
            for (int q = 0; q < 4; ++q) s[n][q] = 0.f;

#pragma unroll
        for (int ks = 0; ks < 4; ++ks) {
            uint32_t kh[4], kl[4];
            ldsm_x4(kh[0], kh[1], kh[2], kh[3],
                    Kb + (lw * 16) * RS + ks * 32 + aoff);
            ldsm_x4(kl[0], kl[1], kl[2], kl[3],
                    Kb + 64 * RS + (lw * 16) * RS + ks * 32 + aoff);
#pragma unroll
            for (int p = 0; p < 4; ++p) {
                uint32_t h0, h1, h2, h3, l0, l1, l2, l3;
                ldsm_x4(h0, h1, h2, h3, Qh + p * 16 * RS + ks * 32 + boff);
                ldsm_x4(l0, l1, l2, l3, Ql + p * 16 * RS + ks * 32 + boff);
                mma_bf16(s[2*p],   kh, h0, h1);
                mma_bf16(s[2*p],   kl, h0, h1);
                mma_bf16(s[2*p],   kh, l0, l1);
                mma_bf16(s[2*p+1], kh, h2, h3);
                mma_bf16(s[2*p+1], kl, h2, h3);
                mma_bf16(s[2*p+1], kh, l2, l3);
            }
        }

        __syncthreads();
        if (more) stageQ(jt + 1);

        if (more) { CPA_WAIT(1); } else { CPA_WAIT(0); }
        __syncthreads();

        // ---- fused per kt: exp(s) -> pack -> O += P_kt . V_kt ----
        const bool diag = (jt == rb);
#pragma unroll
        for (int kt = 0; kt < 4; ++kt) {
            uint32_t pha[4], pla[4];
#pragma unroll
            for (int h = 0; h < 2; ++h) {
                const int n = 2 * kt + h;
                float p0 = __expf(s[n][0]);
                float p1 = __expf(s[n][1]);
                float p2 = __expf(s[n][2]);
                float p3 = __expf(s[n][3]);
                if (diag) {
                    const int col = j0 + 8 * n + 2 * tg;
                    if (col     > rowA)     p0 = 0.f;
                    if (col + 1 > rowA)     p1 = 0.f;
                    if (col     > rowA + 8) p2 = 0.f;
                    if (col + 1 > rowA + 8) p3 = 0.f;
                }
                ellA += p0 + p1;
                ellB += p2 + p3;
                uint32_t h01, l01, h23, l23;
                split_pair(p0, p1, h01, l01);
                split_pair(p2, p3, h23, l23);
                if (h == 0) {
                    pha[0] = h01; pha[1] = h23;
                    pla[0] = l01; pla[1] = l23;
                } else {
                    pha[2] = h01; pha[3] = h23;
                    pla[2] = l01; pla[3] = l23;
                }
            }
#pragma unroll
            for (int p = 0; p < 4; ++p) {
                uint32_t h0, h1, h2, h3, l0, l1, l2, l3;
                ldsm_x4(h0, h1, h2, h3, Vh + p * 16 * RS + kt * 32 + boff);
                ldsm_x4(l0, l1, l2, l3, Vl + p * 16 * RS + kt * 32 + boff);
                mma_bf16(o[2*p],   pha, h0, h1);
                mma_bf16(o[2*p],   pla, h0, h1);
                mma_bf16(o[2*p],   pha, l0, l1);
                mma_bf16(o[2*p+1], pha, h2, h3);
                mma_bf16(o[2*p+1], pla, h2, h3);
                mma_bf16(o[2*p+1], pha, l2, l3);
            }
        }

        __syncthreads();
        if (more) stageV(jt + 1);
    }

    // ---- epilogue ----
    ellA += __shfl_xor_sync(0xffffffffu, ellA, 1);
    ellA += __shfl_xor_sync(0xffffffffu, ellA, 2);
    ellB += __shfl_xor_sync(0xffffffffu, ellB, 1);
    ellB += __shfl_xor_sync(0xffffffffu, ellB, 2);
    if (tg == 0) {
        atomicAdd(&g_ell[b * 4096 + rowA],     ellA);
        atomicAdd(&g_ell[b * 4096 + rowA + 8], ellB);
    }
    float* OA = g_O + (size_t)(b * 4096 + rowA) * 64;
    float* OB = OA + 8 * 64;
#pragma unroll
    for (int n = 0; n < 8; ++n) {
        const int col = 8 * n + 2 * tg;
        redg_v2(OA + col, o[n][0], o[n][1]);
        redg_v2(OB + col, o[n][2], o[n][3]);
    }
}

// ============================================================================
// Divide: out = O / ell
// ============================================================================
__global__ __launch_bounds__(256) void divide_kernel(float* __restrict__ out)
{
    const size_t tid0 = (size_t)blockIdx.x * 256 + threadIdx.x;
    const size_t stride = (size_t)gridDim.x * 256;
    const size_t N = (size_t)MROWS * HH / 4;
    for (size_t u = tid0; u < N; u += stride) {
        const size_t m = u >> 4;
        const float inv = 1.0f / g_ell[m];
        float4 v = ((const float4*)g_O)[u];
        v.x *= inv; v.y *= inv; v.z *= inv; v.w *= inv;
        ((float4*)out)[u] = v;
    }
}

// ============================================================================
extern "C" void kernel_launch(void* const* d_in, const int* in_sizes, int n_in,
                              void* d_out, int out_size)
{
    const float* x  = (const float*)d_in[0];
    const float* Wq = (const float*)d_in[1];
    const float* bq = (const float*)d_in[2];
    const float* Wk = (const float*)d_in[3];
    const float* bk = (const float*)d_in[4];
    const float* Wv = (const float*)d_in[5];
    const float* bv = (const float*)d_in[6];
    float* out = (float*)d_out;

    cudaFuncSetAttribute(proj_kernel, cudaFuncAttributeMaxDynamicSharedMemorySize, PROJ_SMEM);
    cudaFuncSetAttribute(attn_kernel, cudaFuncAttributeMaxDynamicSharedMemorySize, ATTN_SMEM);

    convert_kernel<<<512, 256>>>(Wq, Wk, Wv);
    proj_kernel<<<128, 256, PROJ_SMEM>>>(x, bq, bk, bv);
    attn_kernel<<<4 * 288, 128, ATTN_SMEM>>>();
    divide_kernel<<<1024, 256>>>(out);
}